// round 2
// baseline (speedup 1.0000x reference)
#include <cuda_runtime.h>
#include <cstddef>

// ---------------- problem constants (fixed for this dataset) ----------------
#define BB      8
#define TT      8
#define NN      196
#define DD      768
#define HH      12
#define HD      64
#define TNTOK   (TT*NN)            // 1568
#define MROWS   (BB*TNTOK)         // 12544
#define QKVCOLS (3*DD)             // 2304

// ---------------- scratch (no allocations allowed -> __device__ globals) ----
__device__ float g_qkv[(size_t)MROWS * QKVCOLS];   // raw qkv GEMM output
__device__ float g_y  [(size_t)MROWS * DD];        // attention output (token-major)

// ---------------- SGEMM: C = A(MxK) * B(KxN) [+ bias], row-major ------------
// 128x128 tile, BK=8, 8x8 per thread, 256 threads. M%128==0, N%128==0, K%8==0.
template<bool HAS_BIAS>
__global__ __launch_bounds__(256) void sgemm128(
    const float* __restrict__ A, const float* __restrict__ B,
    const float* __restrict__ bias, float* __restrict__ C,
    int M, int N, int K)
{
    constexpr int BM = 128, BN = 128, BK = 8, TM = 8, TN = 8;
    __shared__ __align__(16) float As[BK * BM];
    __shared__ __align__(16) float Bs[BK * BN];

    const int tid = threadIdx.x;
    const int brow = blockIdx.y, bcol = blockIdx.x;
    const int threadCol = tid % (BN / TN);   // 0..15
    const int threadRow = tid / (BN / TN);   // 0..15

    const float* Ab = A + (size_t)brow * BM * K;
    const float* Bb = B + (size_t)bcol * BN;

    const int innerRowA = tid / (BK / 4);    // 0..127
    const int innerColA = tid % (BK / 4);    // 0..1
    const int innerRowB = tid / (BN / 4);    // 0..7
    const int innerColB = tid % (BN / 4);    // 0..31

    float acc[TM][TN] = {};
    float regM[TM], regN[TN];

    for (int k0 = 0; k0 < K; k0 += BK) {
        float4 a = *(const float4*)(Ab + (size_t)innerRowA * K + k0 + innerColA * 4);
        As[(innerColA * 4 + 0) * BM + innerRowA] = a.x;
        As[(innerColA * 4 + 1) * BM + innerRowA] = a.y;
        As[(innerColA * 4 + 2) * BM + innerRowA] = a.z;
        As[(innerColA * 4 + 3) * BM + innerRowA] = a.w;
        *(float4*)(&Bs[innerRowB * BN + innerColB * 4]) =
            *(const float4*)(Bb + (size_t)(k0 + innerRowB) * N + innerColB * 4);
        __syncthreads();

        #pragma unroll
        for (int k = 0; k < BK; k++) {
            #pragma unroll
            for (int i = 0; i < TM; i += 4)
                *(float4*)&regM[i] = *(const float4*)&As[k * BM + threadRow * TM + i];
            #pragma unroll
            for (int j = 0; j < TN; j += 4)
                *(float4*)&regN[j] = *(const float4*)&Bs[k * BN + threadCol * TN + j];
            #pragma unroll
            for (int i = 0; i < TM; i++)
                #pragma unroll
                for (int j = 0; j < TN; j++)
                    acc[i][j] = fmaf(regM[i], regN[j], acc[i][j]);
        }
        __syncthreads();
    }

    #pragma unroll
    for (int i = 0; i < TM; i++) {
        size_t row = (size_t)brow * BM + threadRow * TM + i;
        float* Crow = C + row * N + (size_t)bcol * BN + threadCol * TN;
        #pragma unroll
        for (int j = 0; j < TN; j += 4) {
            float4 v;
            v.x = acc[i][j + 0]; v.y = acc[i][j + 1];
            v.z = acc[i][j + 2]; v.w = acc[i][j + 3];
            if (HAS_BIAS) {
                const float* bb = bias + (size_t)bcol * BN + threadCol * TN + j;
                v.x += bb[0]; v.y += bb[1]; v.z += bb[2]; v.w += bb[3];
            }
            *(float4*)(Crow + j) = v;
        }
    }
}

// ---------------- spatial attention + temporal mean, per (b,h,t) frame ------
// One block per frame. K,V tiles (196x64 fp32) in SMEM; one query row per lane
// (online softmax, fully register-resident q and o). All SMEM reads in the
// main loop are warp-uniform -> broadcast, conflict-free.
// Temporal branch == softmax over length-1 axis == mean_n V, added at the end.
#define ATT_THREADS 224
#define ATT_SMEM_FLOATS (2 * NN * HD + HD)

__global__ __launch_bounds__(ATT_THREADS, 1) void attn_kernel(
    const float* __restrict__ qkv, float* __restrict__ y)
{
    extern __shared__ float sm[];
    float* Ks    = sm;                 // [196][64]
    float* Vs    = sm + NN * HD;       // [196][64]
    float* vmean = Vs + NN * HD;       // [64]

    const int bid = blockIdx.x;
    const int b = bid / (HH * TT);
    const int h = (bid / TT) % HH;
    const int t = bid % TT;
    const size_t row0 = (size_t)b * TNTOK + (size_t)t * NN;

    const float* qbase = qkv + row0 * QKVCOLS + 0 * DD + h * HD;
    const float* kbase = qkv + row0 * QKVCOLS + 1 * DD + h * HD;
    const float* vbase = qkv + row0 * QKVCOLS + 2 * DD + h * HD;

    const int tid = threadIdx.x;
    for (int idx = tid; idx < NN * (HD / 4); idx += ATT_THREADS) {
        int n = idx / (HD / 4);
        int d4 = idx % (HD / 4);
        *(float4*)&Ks[n * HD + d4 * 4] = *(const float4*)(kbase + (size_t)n * QKVCOLS + d4 * 4);
        *(float4*)&Vs[n * HD + d4 * 4] = *(const float4*)(vbase + (size_t)n * QKVCOLS + d4 * 4);
    }
    __syncthreads();

    if (tid < HD) {
        float s = 0.f;
        for (int n = 0; n < NN; n++) s += Vs[n * HD + tid];
        vmean[tid] = s * (1.0f / NN);
    }
    __syncthreads();

    const int nq = tid;
    if (nq < NN) {
        float qr[HD];
        #pragma unroll
        for (int d4 = 0; d4 < HD / 4; d4++)
            *(float4*)&qr[d4 * 4] = *(const float4*)(qbase + (size_t)nq * QKVCOLS + d4 * 4);

        float o[HD];
        #pragma unroll
        for (int d = 0; d < HD; d++) o[d] = 0.f;
        float m = -1e30f, l = 0.f;
        const float scale = 0.125f;   // hd^-0.5

        for (int j = 0; j < NN; j++) {
            const float* kj = &Ks[j * HD];
            float s0 = 0.f, s1 = 0.f, s2 = 0.f, s3 = 0.f;
            #pragma unroll
            for (int d = 0; d < HD; d += 4) {
                s0 = fmaf(qr[d + 0], kj[d + 0], s0);
                s1 = fmaf(qr[d + 1], kj[d + 1], s1);
                s2 = fmaf(qr[d + 2], kj[d + 2], s2);
                s3 = fmaf(qr[d + 3], kj[d + 3], s3);
            }
            float s = ((s0 + s1) + (s2 + s3)) * scale;
            float mnew  = fmaxf(m, s);
            float alpha = __expf(m - mnew);
            float p     = __expf(s - mnew);
            l = l * alpha + p;
            const float* vj = &Vs[j * HD];
            #pragma unroll
            for (int d = 0; d < HD; d++)
                o[d] = fmaf(o[d], alpha, p * vj[d]);
            m = mnew;
        }

        const float inv = 1.0f / l;
        float* outp = y + (row0 + nq) * DD + h * HD;
        #pragma unroll
        for (int d4 = 0; d4 < HD / 4; d4++) {
            float4 v;
            v.x = o[d4 * 4 + 0] * inv + vmean[d4 * 4 + 0];
            v.y = o[d4 * 4 + 1] * inv + vmean[d4 * 4 + 1];
            v.z = o[d4 * 4 + 2] * inv + vmean[d4 * 4 + 2];
            v.w = o[d4 * 4 + 3] * inv + vmean[d4 * 4 + 3];
            *(float4*)(outp + d4 * 4) = v;
        }
    }
}

// ---------------- launch --------------------------------------------------
extern "C" void kernel_launch(void* const* d_in, const int* in_sizes, int n_in,
                              void* d_out, int out_size)
{
    // Identify inputs by element count (robust to metadata ordering).
    const float* x = nullptr;
    const float* w_qkv = nullptr;
    const float* w_proj = nullptr;
    const float* b_proj = nullptr;
    for (int i = 0; i < n_in; i++) {
        long sz = in_sizes[i];
        if      (sz == (long)MROWS * DD)      { if (!x) x = (const float*)d_in[i]; }
        else if (sz == (long)DD * QKVCOLS)    w_qkv  = (const float*)d_in[i];
        else if (sz == (long)DD * DD)         w_proj = (const float*)d_in[i];
        else if (sz == (long)DD)              b_proj = (const float*)d_in[i];
    }

    void* qkv_ptr = nullptr;
    void* y_ptr   = nullptr;
    cudaGetSymbolAddress(&qkv_ptr, g_qkv);
    cudaGetSymbolAddress(&y_ptr, g_y);

    // 1) QKV projection: (12544 x 768) @ (768 x 2304)
    sgemm128<false><<<dim3(QKVCOLS / 128, MROWS / 128), 256>>>(
        x, w_qkv, nullptr, (float*)qkv_ptr, MROWS, QKVCOLS, DD);

    // 2) per-frame spatial attention + temporal (mean-V) branch
    const size_t smem_bytes = (size_t)ATT_SMEM_FLOATS * sizeof(float);
    cudaFuncSetAttribute(attn_kernel, cudaFuncAttributeMaxDynamicSharedMemorySize,
                         (int)smem_bytes);
    attn_kernel<<<BB * HH * TT, ATT_THREADS, smem_bytes>>>(
        (const float*)qkv_ptr, (float*)y_ptr);

    // 3) output projection + bias: (12544 x 768) @ (768 x 768) + b
    sgemm128<true><<<dim3(DD / 128, MROWS / 128), 256>>>(
        (const float*)y_ptr, w_proj, b_proj, (float*)d_out, MROWS, DD, DD);
}

// round 4
// speedup vs baseline: 1.6773x; 1.6773x over previous
#include <cuda_runtime.h>
#include <cuda_bf16.h>
#include <cstdint>
#include <cstddef>

// ---------------- problem constants ----------------
#define BB      8
#define TT      8
#define NN      196
#define DD      768
#define HH      12
#define HD      64
#define TNTOK   (TT*NN)            // 1568
#define MROWS   (BB*TNTOK)         // 12544
#define QKVCOLS (3*DD)             // 2304

// ---------------- scratch ----------------
__device__ __nv_bfloat16 g_xh[(size_t)MROWS * DD];
__device__ __nv_bfloat16 g_xl[(size_t)MROWS * DD];
__device__ __nv_bfloat16 g_wqkvT_h[(size_t)QKVCOLS * DD];
__device__ __nv_bfloat16 g_wqkvT_l[(size_t)QKVCOLS * DD];
__device__ __nv_bfloat16 g_wprojT_h[(size_t)DD * DD];
__device__ __nv_bfloat16 g_wprojT_l[(size_t)DD * DD];
__device__ float         g_qkv[(size_t)MROWS * QKVCOLS];
__device__ __nv_bfloat16 g_yh[(size_t)MROWS * DD];
__device__ __nv_bfloat16 g_yl[(size_t)MROWS * DD];

// ---------------- helpers ----------------
__device__ __forceinline__ uint32_t smem_u32(const void* p) {
    uint32_t a;
    asm("{ .reg .u64 t; cvta.to.shared.u64 t, %1; cvt.u32.u64 %0, t; }" : "=r"(a) : "l"(p));
    return a;
}
__device__ __forceinline__ void mma16816(float* c, const uint32_t* a, const uint32_t* b) {
    asm volatile(
        "mma.sync.aligned.m16n8k16.row.col.f32.bf16.bf16.f32 "
        "{%0,%1,%2,%3}, {%4,%5,%6,%7}, {%8,%9}, {%0,%1,%2,%3};"
        : "+f"(c[0]), "+f"(c[1]), "+f"(c[2]), "+f"(c[3])
        : "r"(a[0]), "r"(a[1]), "r"(a[2]), "r"(a[3]), "r"(b[0]), "r"(b[1]));
}
#define CP_ASYNC16(dst, src) \
    asm volatile("cp.async.cg.shared.global [%0], [%1], 16;" :: "r"(dst), "l"(src))
#define CP_COMMIT() asm volatile("cp.async.commit_group;" ::: "memory")

// ---------------- prep: fp32 -> bf16 hi/lo split (elementwise) --------------
__global__ __launch_bounds__(256) void convert_split(
    const float* __restrict__ src, __nv_bfloat16* __restrict__ dh,
    __nv_bfloat16* __restrict__ dl, int n4)
{
    int i = blockIdx.x * blockDim.x + threadIdx.x;
    if (i >= n4) return;
    float4 v = *(const float4*)(src + (size_t)i * 4);
    __nv_bfloat16 h0 = __float2bfloat16(v.x), h1 = __float2bfloat16(v.y);
    __nv_bfloat16 h2 = __float2bfloat16(v.z), h3 = __float2bfloat16(v.w);
    __nv_bfloat16 l0 = __float2bfloat16(v.x - __bfloat162float(h0));
    __nv_bfloat16 l1 = __float2bfloat16(v.y - __bfloat162float(h1));
    __nv_bfloat16 l2 = __float2bfloat16(v.z - __bfloat162float(h2));
    __nv_bfloat16 l3 = __float2bfloat16(v.w - __bfloat162float(h3));
    *(__nv_bfloat162*)(dh + (size_t)i * 4 + 0) = {h0, h1};
    *(__nv_bfloat162*)(dh + (size_t)i * 4 + 2) = {h2, h3};
    *(__nv_bfloat162*)(dl + (size_t)i * 4 + 0) = {l0, l1};
    *(__nv_bfloat162*)(dl + (size_t)i * 4 + 2) = {l2, l3};
}

// ---------------- prep: transpose weights [K][N] -> [N][K] + hi/lo split ----
__global__ __launch_bounds__(256) void transpose_split(
    const float* __restrict__ src, __nv_bfloat16* __restrict__ dh,
    __nv_bfloat16* __restrict__ dl, int K, int N)
{
    __shared__ float t[32][33];
    int n0 = blockIdx.x * 32, k0 = blockIdx.y * 32;
    int tx = threadIdx.x, ty = threadIdx.y;   // block (32, 8)
    #pragma unroll
    for (int j = ty; j < 32; j += 8)
        t[j][tx] = src[(size_t)(k0 + j) * N + n0 + tx];
    __syncthreads();
    #pragma unroll
    for (int j = ty; j < 32; j += 8) {
        float v = t[tx][j];                    // element (k0+tx, n0+j)
        __nv_bfloat16 h = __float2bfloat16(v);
        __nv_bfloat16 l = __float2bfloat16(v - __bfloat162float(h));
        size_t o = (size_t)(n0 + j) * K + k0 + tx;
        dh[o] = h; dl[o] = l;
    }
}

// ---------------- split-bf16 HMMA GEMM: C = (Ah+Al)(Bh+Bl)^T [+bias] --------
// A*: [M][K] bf16 row-major; B*: [N][K] bf16 row-major.
// 128x128 block tile, BK=32, 8 warps (2x4), warp tile 64x32,
// mma.sync.m16n8k16 bf16 with fp32 acc, 3-term Ootomo accumulation,
// cp.async double-buffered SMEM, padded rows (stride 40 bf16 = 80B).
#define G_BK        32
#define G_ROWB      80                      // padded row bytes (40 bf16)
#define G_TILE_B    (128 * G_ROWB)          // 10240 B per operand tile
#define G_STAGE_B   (4 * G_TILE_B)          // Ah, Al, Bh, Bl
#define G_SMEM      (2 * G_STAGE_B)         // 81920 B

__global__ __launch_bounds__(256) void gemm_split_hmma(
    const __nv_bfloat16* __restrict__ Ah, const __nv_bfloat16* __restrict__ Al,
    const __nv_bfloat16* __restrict__ Bh, const __nv_bfloat16* __restrict__ Bl,
    const float* __restrict__ bias, float* __restrict__ C, int Ncols, int K)
{
    extern __shared__ char sm[];
    const int tid  = threadIdx.x;
    const int lane = tid & 31;
    const int wid  = tid >> 5;
    const int warp_m = wid >> 2;      // 0..1 -> m offset *64
    const int warp_n = wid & 3;       // 0..3 -> n offset *32
    const int g   = lane >> 2;        // group row 0..7
    const int tig = lane & 3;         // thread-in-group 0..3

    const size_t arow0 = (size_t)blockIdx.y * 128;
    const size_t brow0 = (size_t)blockIdx.x * 128;

    const __nv_bfloat16* gA[4] = {
        Ah + arow0 * K, Al + arow0 * K, Bh + brow0 * K, Bl + brow0 * K };

    // each thread copies 8 x 16B per stage (4 tiles * 512 chunks / 256 thr)
    const int lrow = tid >> 2;        // 0..63
    const int c16  = tid & 3;         // 16B chunk in 64B row payload
    auto load_stage = [&](int s, int k0) {
        char* base = sm + s * G_STAGE_B;
        #pragma unroll
        for (int i = 0; i < 8; i++) {
            const int t   = i >> 1;               // operand tile (compile-time)
            const int row = (i & 1) * 64 + lrow;  // 0..127
            const __nv_bfloat16* src = gA[t] + (size_t)row * K + k0 + c16 * 8;
            uint32_t dst = smem_u32(base + t * G_TILE_B + row * G_ROWB + c16 * 16);
            CP_ASYNC16(dst, src);
        }
        CP_COMMIT();
    };

    float acc[4][4][4];
    #pragma unroll
    for (int mt = 0; mt < 4; mt++)
        #pragma unroll
        for (int nt = 0; nt < 4; nt++)
            #pragma unroll
            for (int i = 0; i < 4; i++) acc[mt][nt][i] = 0.f;

    load_stage(0, 0);

    const int KT = K / G_BK;
    for (int kt = 0; kt < KT; kt++) {
        if (kt + 1 < KT) {
            load_stage((kt + 1) & 1, (kt + 1) * G_BK);
            asm volatile("cp.async.wait_group 1;" ::: "memory");
        } else {
            asm volatile("cp.async.wait_group 0;" ::: "memory");
        }
        __syncthreads();

        char* sb = sm + (kt & 1) * G_STAGE_B;
        char* sAh = sb + 0 * G_TILE_B;
        char* sAl = sb + 1 * G_TILE_B;
        char* sBh = sb + 2 * G_TILE_B;
        char* sBl = sb + 3 * G_TILE_B;

        #pragma unroll
        for (int ks = 0; ks < 2; ks++) {
            const int kb = (ks * 16 + tig * 2) * 2;   // byte offset of k pair
            uint32_t ah[4][4], al[4][4], bh[4][2], bl[4][2];
            #pragma unroll
            for (int mt = 0; mt < 4; mt++) {
                int r = warp_m * 64 + mt * 16 + g;
                ah[mt][0] = *(const uint32_t*)(sAh + r * G_ROWB + kb);
                ah[mt][1] = *(const uint32_t*)(sAh + (r + 8) * G_ROWB + kb);
                ah[mt][2] = *(const uint32_t*)(sAh + r * G_ROWB + kb + 16);
                ah[mt][3] = *(const uint32_t*)(sAh + (r + 8) * G_ROWB + kb + 16);
                al[mt][0] = *(const uint32_t*)(sAl + r * G_ROWB + kb);
                al[mt][1] = *(const uint32_t*)(sAl + (r + 8) * G_ROWB + kb);
                al[mt][2] = *(const uint32_t*)(sAl + r * G_ROWB + kb + 16);
                al[mt][3] = *(const uint32_t*)(sAl + (r + 8) * G_ROWB + kb + 16);
            }
            #pragma unroll
            for (int nt = 0; nt < 4; nt++) {
                int r = warp_n * 32 + nt * 8 + g;
                bh[nt][0] = *(const uint32_t*)(sBh + r * G_ROWB + kb);
                bh[nt][1] = *(const uint32_t*)(sBh + r * G_ROWB + kb + 16);
                bl[nt][0] = *(const uint32_t*)(sBl + r * G_ROWB + kb);
                bl[nt][1] = *(const uint32_t*)(sBl + r * G_ROWB + kb + 16);
            }
            #pragma unroll
            for (int mt = 0; mt < 4; mt++)
                #pragma unroll
                for (int nt = 0; nt < 4; nt++) {
                    mma16816(acc[mt][nt], ah[mt], bh[nt]);
                    mma16816(acc[mt][nt], ah[mt], bl[nt]);
                    mma16816(acc[mt][nt], al[mt], bh[nt]);
                }
        }
        __syncthreads();
    }

    // epilogue: fp32 direct to gmem (+bias)
    const size_t col0 = (size_t)blockIdx.x * 128 + warp_n * 32;
    #pragma unroll
    for (int mt = 0; mt < 4; mt++) {
        size_t row = arow0 + warp_m * 64 + mt * 16 + g;
        #pragma unroll
        for (int nt = 0; nt < 4; nt++) {
            size_t col = col0 + nt * 8 + tig * 2;
            float b0 = 0.f, b1 = 0.f;
            if (bias) { b0 = bias[col]; b1 = bias[col + 1]; }
            float2 v0 = { acc[mt][nt][0] + b0, acc[mt][nt][1] + b1 };
            float2 v1 = { acc[mt][nt][2] + b0, acc[mt][nt][3] + b1 };
            *(float2*)(C + row * Ncols + col)       = v0;
            *(float2*)(C + (row + 8) * Ncols + col) = v1;
        }
    }
}

// ---------------- spatial attention + temporal mean, per (b,h,t) frame ------
// fp32 math; epilogue emits hi/lo bf16 for the split proj GEMM.
#define ATT_THREADS 224
#define ATT_SMEM_FLOATS (2 * NN * HD + HD)

__global__ __launch_bounds__(ATT_THREADS, 1) void attn_kernel(
    const float* __restrict__ qkv,
    __nv_bfloat16* __restrict__ yh, __nv_bfloat16* __restrict__ yl)
{
    extern __shared__ float smf[];
    float* Ks    = smf;
    float* Vs    = smf + NN * HD;
    float* vmean = Vs + NN * HD;

    const int bid = blockIdx.x;
    const int b = bid / (HH * TT);
    const int h = (bid / TT) % HH;
    const int t = bid % TT;
    const size_t row0 = (size_t)b * TNTOK + (size_t)t * NN;

    const float* qbase = qkv + row0 * QKVCOLS + 0 * DD + h * HD;
    const float* kbase = qkv + row0 * QKVCOLS + 1 * DD + h * HD;
    const float* vbase = qkv + row0 * QKVCOLS + 2 * DD + h * HD;

    const int tid = threadIdx.x;
    for (int idx = tid; idx < NN * (HD / 4); idx += ATT_THREADS) {
        int n = idx / (HD / 4);
        int d4 = idx % (HD / 4);
        *(float4*)&Ks[n * HD + d4 * 4] = *(const float4*)(kbase + (size_t)n * QKVCOLS + d4 * 4);
        *(float4*)&Vs[n * HD + d4 * 4] = *(const float4*)(vbase + (size_t)n * QKVCOLS + d4 * 4);
    }
    __syncthreads();

    if (tid < HD) {
        float s = 0.f;
        for (int n = 0; n < NN; n++) s += Vs[n * HD + tid];
        vmean[tid] = s * (1.0f / NN);
    }
    __syncthreads();

    const int nq = tid;
    if (nq < NN) {
        float qr[HD];
        #pragma unroll
        for (int d4 = 0; d4 < HD / 4; d4++)
            *(float4*)&qr[d4 * 4] = *(const float4*)(qbase + (size_t)nq * QKVCOLS + d4 * 4);

        float o[HD];
        #pragma unroll
        for (int d = 0; d < HD; d++) o[d] = 0.f;
        float m = -1e30f, l = 0.f;
        const float scale = 0.125f;

        for (int j = 0; j < NN; j++) {
            const float* kj = &Ks[j * HD];
            float s0 = 0.f, s1 = 0.f, s2 = 0.f, s3 = 0.f;
            #pragma unroll
            for (int d = 0; d < HD; d += 4) {
                s0 = fmaf(qr[d + 0], kj[d + 0], s0);
                s1 = fmaf(qr[d + 1], kj[d + 1], s1);
                s2 = fmaf(qr[d + 2], kj[d + 2], s2);
                s3 = fmaf(qr[d + 3], kj[d + 3], s3);
            }
            float s = ((s0 + s1) + (s2 + s3)) * scale;
            float mnew  = fmaxf(m, s);
            float alpha = __expf(m - mnew);
            float p     = __expf(s - mnew);
            l = l * alpha + p;
            const float* vj = &Vs[j * HD];
            #pragma unroll
            for (int d = 0; d < HD; d++)
                o[d] = fmaf(o[d], alpha, p * vj[d]);
            m = mnew;
        }

        const float inv = 1.0f / l;
        const size_t obase = (row0 + nq) * DD + h * HD;
        #pragma unroll
        for (int d = 0; d < HD; d += 2) {
            float v0 = o[d + 0] * inv + vmean[d + 0];
            float v1 = o[d + 1] * inv + vmean[d + 1];
            __nv_bfloat16 h0 = __float2bfloat16(v0);
            __nv_bfloat16 h1 = __float2bfloat16(v1);
            __nv_bfloat16 l0 = __float2bfloat16(v0 - __bfloat162float(h0));
            __nv_bfloat16 l1 = __float2bfloat16(v1 - __bfloat162float(h1));
            *(__nv_bfloat162*)(yh + obase + d) = {h0, h1};
            *(__nv_bfloat162*)(yl + obase + d) = {l0, l1};
        }
    }
}

// ---------------- launch --------------------------------------------------
extern "C" void kernel_launch(void* const* d_in, const int* in_sizes, int n_in,
                              void* d_out, int out_size)
{
    const float* x = nullptr;
    const float* w_qkv = nullptr;
    const float* w_proj = nullptr;
    const float* b_proj = nullptr;
    for (int i = 0; i < n_in; i++) {
        long sz = in_sizes[i];
        if      (sz == (long)MROWS * DD)   { if (!x) x = (const float*)d_in[i]; }
        else if (sz == (long)DD * QKVCOLS) w_qkv  = (const float*)d_in[i];
        else if (sz == (long)DD * DD)      w_proj = (const float*)d_in[i];
        else if (sz == (long)DD)           b_proj = (const float*)d_in[i];
    }

    void *xh, *xl, *wqh, *wql, *wph, *wpl, *qkv, *yh, *yl;
    cudaGetSymbolAddress(&xh, g_xh);   cudaGetSymbolAddress(&xl, g_xl);
    cudaGetSymbolAddress(&wqh, g_wqkvT_h); cudaGetSymbolAddress(&wql, g_wqkvT_l);
    cudaGetSymbolAddress(&wph, g_wprojT_h); cudaGetSymbolAddress(&wpl, g_wprojT_l);
    cudaGetSymbolAddress(&qkv, g_qkv);
    cudaGetSymbolAddress(&yh, g_yh);   cudaGetSymbolAddress(&yl, g_yl);

    // prep: split x, transpose+split weights
    {
        int n4 = MROWS * DD / 4;
        convert_split<<<(n4 + 255) / 256, 256>>>(x, (__nv_bfloat16*)xh, (__nv_bfloat16*)xl, n4);
        transpose_split<<<dim3(QKVCOLS / 32, DD / 32), dim3(32, 8)>>>(
            w_qkv, (__nv_bfloat16*)wqh, (__nv_bfloat16*)wql, DD, QKVCOLS);
        transpose_split<<<dim3(DD / 32, DD / 32), dim3(32, 8)>>>(
            w_proj, (__nv_bfloat16*)wph, (__nv_bfloat16*)wpl, DD, DD);
    }

    cudaFuncSetAttribute(gemm_split_hmma, cudaFuncAttributeMaxDynamicSharedMemorySize, G_SMEM);

    // 1) QKV projection (split-bf16 HMMA): (12544 x 768) @ (768 x 2304)
    gemm_split_hmma<<<dim3(QKVCOLS / 128, MROWS / 128), 256, G_SMEM>>>(
        (const __nv_bfloat16*)xh, (const __nv_bfloat16*)xl,
        (const __nv_bfloat16*)wqh, (const __nv_bfloat16*)wql,
        nullptr, (float*)qkv, QKVCOLS, DD);

    // 2) per-frame attention (fp32), emits split-bf16 y
    const size_t att_smem = (size_t)ATT_SMEM_FLOATS * sizeof(float);
    cudaFuncSetAttribute(attn_kernel, cudaFuncAttributeMaxDynamicSharedMemorySize, (int)att_smem);
    attn_kernel<<<BB * HH * TT, ATT_THREADS, att_smem>>>(
        (const float*)qkv, (__nv_bfloat16*)yh, (__nv_bfloat16*)yl);

    // 3) output projection + bias (split-bf16 HMMA): (12544 x 768) @ (768 x 768)
    gemm_split_hmma<<<dim3(DD / 128, MROWS / 128), 256, G_SMEM>>>(
        (const __nv_bfloat16*)yh, (const __nv_bfloat16*)yl,
        (const __nv_bfloat16*)wph, (const __nv_bfloat16*)wpl,
        b_proj, (float*)d_out, DD, DD);
}